// round 1
// baseline (speedup 1.0000x reference)
#include <cuda_runtime.h>

#define B_  16
#define N_  4096
#define D_  1024
#define K_  2048
#define P_  (N_ - K_)   // 2048 pruned tokens per batch
#define RC_ 8           // row chunks for pruned sum

__device__ int   g_topidx[B_ * K_];
__device__ int   g_prunedidx[B_ * P_];
__device__ float g_partial[RC_ * B_ * D_];

// -------------------------------------------------------------------------
// Kernel A: exact descending rank of every attn weight (stable tie-break on
// index, matching jax.lax.top_k). Writes selected positions and a compacted
// pruned-index list. grid (B_, N_/1024), block 1024.
// -------------------------------------------------------------------------
__global__ void rank_kernel(const float* __restrict__ attn) {
    __shared__ float sv[N_];
    const int b = blockIdx.x;
    const int t = threadIdx.x;

    #pragma unroll
    for (int p = 0; p < N_ / 1024; p++)
        sv[t + p * 1024] = attn[b * N_ + t + p * 1024];
    __syncthreads();

    const int   i  = blockIdx.y * 1024 + t;
    const float vi = sv[i];
    int rank = 0;
    #pragma unroll 8
    for (int j = 0; j < N_; j++) {
        const float vj = sv[j];
        rank += (vj > vi) || (vj == vi && j < i);
    }

    if (rank < K_) g_topidx[b * K_ + rank]          = i;
    else           g_prunedidx[b * P_ + (rank - K_)] = i;
}

// -------------------------------------------------------------------------
// Kernel B: gather selected rows into out[b, 0..K-1, :].
// grid (K_/4, B_), block 256. Each block copies 4 rows of 1024 floats
// (float4 vectorized, fully coalesced).
// -------------------------------------------------------------------------
__global__ void gather_kernel(const float* __restrict__ seq,
                              float* __restrict__ out) {
    const int b  = blockIdx.y;
    const int r0 = blockIdx.x * 4;
    const int t  = threadIdx.x;

    #pragma unroll
    for (int rr = 0; rr < 4; rr++) {
        const int r = r0 + rr;
        const int n = g_topidx[b * K_ + r];
        const float4* __restrict__ src =
            reinterpret_cast<const float4*>(seq + ((size_t)(b * N_ + n)) * D_);
        float4* __restrict__ dst =
            reinterpret_cast<float4*>(out + ((size_t)(b * (K_ + 1) + r)) * D_);
        dst[t] = src[t];
    }
}

// -------------------------------------------------------------------------
// Kernel C: partial column-sums of pruned rows.
// grid (B_, D_/256, RC_), block 256. Each block sums P_/RC_ = 256 rows
// over a 256-column slice into registers, stores its own partial slot
// (no atomics -> deterministic, no init needed).
// -------------------------------------------------------------------------
__global__ void prunesum_kernel(const float* __restrict__ seq) {
    const int b   = blockIdx.x;
    const int col = blockIdx.y * 256 + threadIdx.x;
    const int rc  = blockIdx.z;
    const int base = b * P_ + rc * (P_ / RC_);

    float acc = 0.0f;
    #pragma unroll 4
    for (int r = 0; r < P_ / RC_; r++) {
        const int n = g_prunedidx[base + r];
        acc += __ldg(seq + ((size_t)(b * N_ + n)) * D_ + col);
    }
    g_partial[((size_t)rc * B_ + b) * D_ + col] = acc;
}

// -------------------------------------------------------------------------
// Kernel D: reduce partials, write mixup row out[b, K, :].
// grid (B_, D_/256), block 256.
// rem_cnt = 2048 + 1e-10 == 2048.0f in fp32.
// -------------------------------------------------------------------------
__global__ void rem_kernel(float* __restrict__ out) {
    const int b   = blockIdx.x;
    const int col = blockIdx.y * 256 + threadIdx.x;

    float s = 0.0f;
    #pragma unroll
    for (int rc = 0; rc < RC_; rc++)
        s += g_partial[((size_t)rc * B_ + b) * D_ + col];

    out[((size_t)(b * (K_ + 1) + K_)) * D_ + col] = 0.05f * s / 2048.0f;
}

extern "C" void kernel_launch(void* const* d_in, const int* in_sizes, int n_in,
                              void* d_out, int out_size) {
    const float* seq  = (const float*)d_in[0];   // (16, 4096, 1024) fp32
    const float* attn = (const float*)d_in[1];   // (16, 4096) fp32
    float* out = (float*)d_out;                  // (16, 2049, 1024) fp32
    (void)in_sizes; (void)n_in; (void)out_size;

    rank_kernel   <<<dim3(B_, N_ / 1024), 1024>>>(attn);
    gather_kernel <<<dim3(K_ / 4, B_),     256>>>(seq, out);
    prunesum_kernel<<<dim3(B_, D_ / 256, RC_), 256>>>(seq);
    rem_kernel    <<<dim3(B_, D_ / 256),   256>>>(out);
}

// round 2
// speedup vs baseline: 1.4180x; 1.4180x over previous
#include <cuda_runtime.h>

#define B_  16
#define N_  4096
#define D_  1024
#define K_  2048
#define P_  (N_ - K_)

#define IC_ 4            // i chunks of 1024
#define JC_ 4            // j chunks of 1024
#define TOK_ 32          // tokens per fused block
#define BLKS_PER_B_ (N_ / TOK_)   // 128

__device__ int   g_rankpart[B_ * JC_ * N_];
__device__ int   g_rank[B_ * N_];
__device__ float g_partial[B_ * BLKS_PER_B_ * D_];

// -------------------------------------------------------------------------
// Kernel A: partial descending rank. grid (B, IC, JC), block 256.
// Each thread handles 4 i's (strided by 256), looping over a 1024-wide
// j-chunk held in smem. Tie-break (j<i, matching jax.lax.top_k stable
// descending order) is uniform per block: jc<ic => all j<i => count >=,
// jc>ic => count >, diagonal => full tie compare.
// -------------------------------------------------------------------------
__global__ void rank_part_kernel(const float* __restrict__ attn) {
    __shared__ float sj[1024];
    const int b  = blockIdx.x;
    const int ic = blockIdx.y;
    const int jc = blockIdx.z;
    const int t  = threadIdx.x;

    #pragma unroll
    for (int p = 0; p < 4; p++)
        sj[t + p * 256] = attn[b * N_ + jc * 1024 + t + p * 256];
    __syncthreads();

    const int ibase = ic * 1024;
    float vi[4];
    int   cnt[4] = {0, 0, 0, 0};
    #pragma unroll
    for (int x = 0; x < 4; x++)
        vi[x] = attn[b * N_ + ibase + x * 256 + t];

    if (jc < ic) {
        // all j < i : count vj >= vi
        #pragma unroll 4
        for (int j = 0; j < 1024; j++) {
            const float vj = sj[j];
            #pragma unroll
            for (int x = 0; x < 4; x++) cnt[x] += (vj >= vi[x]);
        }
    } else if (jc > ic) {
        // all j > i : count vj > vi
        #pragma unroll 4
        for (int j = 0; j < 1024; j++) {
            const float vj = sj[j];
            #pragma unroll
            for (int x = 0; x < 4; x++) cnt[x] += (vj > vi[x]);
        }
    } else {
        // diagonal: local index comparison decides ties
        #pragma unroll 2
        for (int j = 0; j < 1024; j++) {
            const float vj = sj[j];
            #pragma unroll
            for (int x = 0; x < 4; x++) {
                const int iloc = x * 256 + t;
                cnt[x] += (vj > vi[x]) || (vj == vi[x] && j < iloc);
            }
        }
    }

    #pragma unroll
    for (int x = 0; x < 4; x++)
        g_rankpart[(b * JC_ + jc) * N_ + ibase + x * 256 + t] = cnt[x];
}

// -------------------------------------------------------------------------
// Kernel B: combine partial ranks. grid (B, 4), block 1024.
// -------------------------------------------------------------------------
__global__ void combine_kernel() {
    const int b = blockIdx.x;
    const int i = blockIdx.y * 1024 + threadIdx.x;
    int r = 0;
    #pragma unroll
    for (int jc = 0; jc < JC_; jc++)
        r += g_rankpart[(b * JC_ + jc) * N_ + i];
    g_rank[b * N_ + i] = r;
}

// -------------------------------------------------------------------------
// Kernel C: fused gather + pruned-sum. grid (BLKS_PER_B, B), block 256.
// Streams TOK_ consecutive token rows (sequential 128KB read per block).
// Per-token branch is uniform across the block (no divergence):
//   rank < K : write row to out[b, rank, :]
//   else     : accumulate into per-thread float4 partial
// -------------------------------------------------------------------------
__global__ void fused_kernel(const float* __restrict__ seq,
                             float* __restrict__ out) {
    const int b   = blockIdx.y;
    const int blk = blockIdx.x;
    const int t   = threadIdx.x;
    const int n0  = blk * TOK_;

    const float4* __restrict__ src =
        reinterpret_cast<const float4*>(seq + ((size_t)(b * N_ + n0)) * D_);
    const int* __restrict__ rnk = g_rank + b * N_ + n0;

    float4 acc = make_float4(0.f, 0.f, 0.f, 0.f);

    #pragma unroll 4
    for (int k = 0; k < TOK_; k++) {
        const float4 v = src[k * (D_ / 4) + t];
        const int r = rnk[k];
        if (r < K_) {
            reinterpret_cast<float4*>(
                out + ((size_t)(b * (K_ + 1) + r)) * D_)[t] = v;
        } else {
            acc.x += v.x; acc.y += v.y; acc.z += v.z; acc.w += v.w;
        }
    }

    reinterpret_cast<float4*>(g_partial)
        [((size_t)b * BLKS_PER_B_ + blk) * (D_ / 4) + t] = acc;
}

// -------------------------------------------------------------------------
// Kernel D: reduce partials, write mixup row out[b, K, :]. grid (B), block 256.
// rem_cnt = 2048 + 1e-10 == 2048.0f in fp32.
// -------------------------------------------------------------------------
__global__ void rem_kernel(float* __restrict__ out) {
    const int b = blockIdx.x;
    const int t = threadIdx.x;

    const float4* __restrict__ p =
        reinterpret_cast<const float4*>(g_partial) +
        (size_t)b * BLKS_PER_B_ * (D_ / 4) + t;

    float4 s = make_float4(0.f, 0.f, 0.f, 0.f);
    #pragma unroll 8
    for (int blk = 0; blk < BLKS_PER_B_; blk++) {
        const float4 v = p[(size_t)blk * (D_ / 4)];
        s.x += v.x; s.y += v.y; s.z += v.z; s.w += v.w;
    }

    const float sc = 0.05f / 2048.0f;
    float4 o = make_float4(s.x * sc, s.y * sc, s.z * sc, s.w * sc);
    reinterpret_cast<float4*>(out + ((size_t)(b * (K_ + 1) + K_)) * D_)[t] = o;
}

extern "C" void kernel_launch(void* const* d_in, const int* in_sizes, int n_in,
                              void* d_out, int out_size) {
    const float* seq  = (const float*)d_in[0];   // (16, 4096, 1024) fp32
    const float* attn = (const float*)d_in[1];   // (16, 4096) fp32
    float* out = (float*)d_out;                  // (16, 2049, 1024) fp32
    (void)in_sizes; (void)n_in; (void)out_size;

    rank_part_kernel<<<dim3(B_, IC_, JC_), 256>>>(attn);
    combine_kernel  <<<dim3(B_, N_ / 1024), 1024>>>();
    fused_kernel    <<<dim3(BLKS_PER_B_, B_), 256>>>(seq, out);
    rem_kernel      <<<B_, 256>>>(out);
}

// round 3
// speedup vs baseline: 1.5679x; 1.1057x over previous
#include <cuda_runtime.h>

#define B_  16
#define N_  4096
#define D_  1024
#define K_  2048
#define P_  (N_ - K_)

#define IC_ 4            // i chunks of 1024
#define JC_ 4            // j chunks of 1024
#define TOK_ 32          // tokens per fused block
#define BLKS_PER_B_ (N_ / TOK_)   // 128

__device__ int   g_rankpart[B_ * JC_ * N_];
__device__ float g_partial[B_ * BLKS_PER_B_ * D_];

// -------------------------------------------------------------------------
// Kernel A: partial descending rank. grid (B, IC, JC), block 256.
// Each thread handles 4 i's (strided by 256), looping over a 1024-wide
// j-chunk held in smem. Tie-break (j<i, matching jax.lax.top_k stable
// descending order) is uniform per block: jc<ic => all j<i => count >=,
// jc>ic => count >, diagonal => full tie compare.
// -------------------------------------------------------------------------
__global__ void __launch_bounds__(256)
rank_part_kernel(const float* __restrict__ attn) {
    __shared__ float sj[1024];
    const int b  = blockIdx.x;
    const int ic = blockIdx.y;
    const int jc = blockIdx.z;
    const int t  = threadIdx.x;

    #pragma unroll
    for (int p = 0; p < 4; p++)
        sj[t + p * 256] = attn[b * N_ + jc * 1024 + t + p * 256];
    __syncthreads();

    const int ibase = ic * 1024;
    float vi[4];
    int   cnt[4] = {0, 0, 0, 0};
    #pragma unroll
    for (int x = 0; x < 4; x++)
        vi[x] = attn[b * N_ + ibase + x * 256 + t];

    if (jc < ic) {
        #pragma unroll 4
        for (int j = 0; j < 1024; j++) {
            const float vj = sj[j];
            #pragma unroll
            for (int x = 0; x < 4; x++) cnt[x] += (vj >= vi[x]);
        }
    } else if (jc > ic) {
        #pragma unroll 4
        for (int j = 0; j < 1024; j++) {
            const float vj = sj[j];
            #pragma unroll
            for (int x = 0; x < 4; x++) cnt[x] += (vj > vi[x]);
        }
    } else {
        #pragma unroll 2
        for (int j = 0; j < 1024; j++) {
            const float vj = sj[j];
            #pragma unroll
            for (int x = 0; x < 4; x++) {
                const int iloc = x * 256 + t;
                cnt[x] += (vj > vi[x]) || (vj == vi[x] && j < iloc);
            }
        }
    }

    #pragma unroll
    for (int x = 0; x < 4; x++)
        g_rankpart[(b * JC_ + jc) * N_ + ibase + x * 256 + t] = cnt[x];
}

// -------------------------------------------------------------------------
// Kernel B: fused gather + pruned-sum. grid (BLKS_PER_B, B), block 256.
// Streams TOK_ consecutive token rows (sequential 128KB read per block).
// Rank is computed inline as the sum of the 4 jc partials (uniform loads,
// amortized over a 4KB row). Per-token branch is uniform across the block:
//   rank < K : write row to out[b, rank, :]
//   else     : accumulate into per-thread float4 partial
// -------------------------------------------------------------------------
__global__ void __launch_bounds__(256)
fused_kernel(const float* __restrict__ seq, float* __restrict__ out) {
    const int b   = blockIdx.y;
    const int blk = blockIdx.x;
    const int t   = threadIdx.x;
    const int n0  = blk * TOK_;

    const float4* __restrict__ src =
        reinterpret_cast<const float4*>(seq + ((size_t)(b * N_ + n0)) * D_);
    const int* __restrict__ rp = g_rankpart + b * JC_ * N_ + n0;

    float4 acc = make_float4(0.f, 0.f, 0.f, 0.f);

    #pragma unroll 8
    for (int k = 0; k < TOK_; k++) {
        const float4 v = src[k * (D_ / 4) + t];
        const int r = rp[k] + rp[N_ + k] + rp[2 * N_ + k] + rp[3 * N_ + k];
        if (r < K_) {
            reinterpret_cast<float4*>(
                out + ((size_t)(b * (K_ + 1) + r)) * D_)[t] = v;
        } else {
            acc.x += v.x; acc.y += v.y; acc.z += v.z; acc.w += v.w;
        }
    }

    reinterpret_cast<float4*>(g_partial)
        [((size_t)b * BLKS_PER_B_ + blk) * (D_ / 4) + t] = acc;
}

// -------------------------------------------------------------------------
// Kernel C: reduce partials, write mixup row out[b, K, :].
// grid (B, 16), block 256: each block owns 16 float4 column-groups
// (64 floats); 16 threads per group each sum 8 of the 128 partials,
// then a smem tree finishes. 256 blocks -> full-chip parallelism.
// rem_cnt = 2048 + 1e-10 == 2048.0f in fp32.
// -------------------------------------------------------------------------
__global__ void __launch_bounds__(256)
rem_kernel(float* __restrict__ out) {
    const int b  = blockIdx.x;
    const int g  = threadIdx.x & 15;         // f4 group within block
    const int s  = threadIdx.x >> 4;         // slice 0..15
    const int c4 = blockIdx.y * 16 + g;      // global f4 column (0..255)

    const float4* __restrict__ p =
        reinterpret_cast<const float4*>(g_partial) +
        (size_t)b * BLKS_PER_B_ * (D_ / 4) + c4;

    float4 a = make_float4(0.f, 0.f, 0.f, 0.f);
    #pragma unroll
    for (int m = 0; m < 8; m++) {
        const float4 v = p[(size_t)(s + 16 * m) * (D_ / 4)];
        a.x += v.x; a.y += v.y; a.z += v.z; a.w += v.w;
    }

    __shared__ float4 red[16][16];
    red[s][g] = a;
    __syncthreads();

    #pragma unroll
    for (int step = 8; step >= 1; step >>= 1) {
        if (s < step) {
            float4 o = red[s + step][g];
            red[s][g].x += o.x; red[s][g].y += o.y;
            red[s][g].z += o.z; red[s][g].w += o.w;
        }
        __syncthreads();
    }

    if (s == 0) {
        const float sc = 0.05f / 2048.0f;
        float4 r = red[0][g];
        r.x *= sc; r.y *= sc; r.z *= sc; r.w *= sc;
        reinterpret_cast<float4*>(
            out + ((size_t)(b * (K_ + 1) + K_)) * D_)[c4] = r;
    }
}

extern "C" void kernel_launch(void* const* d_in, const int* in_sizes, int n_in,
                              void* d_out, int out_size) {
    const float* seq  = (const float*)d_in[0];   // (16, 4096, 1024) fp32
    const float* attn = (const float*)d_in[1];   // (16, 4096) fp32
    float* out = (float*)d_out;                  // (16, 2049, 1024) fp32
    (void)in_sizes; (void)n_in; (void)out_size;

    rank_part_kernel<<<dim3(B_, IC_, JC_), 256>>>(attn);
    fused_kernel    <<<dim3(BLKS_PER_B_, B_), 256>>>(seq, out);
    rem_kernel      <<<dim3(B_, 16), 256>>>(out);
}

// round 4
// speedup vs baseline: 1.7016x; 1.0853x over previous
#include <cuda_runtime.h>

#define B_  16
#define N_  4096
#define D_  1024
#define K_  2048

#define IC_ 4            // i chunks of 1024
#define JC_ 8            // j chunks of 512
#define TOK_ 32          // tokens per fused block
#define BLKS_PER_B_ (N_ / TOK_)   // 128

__device__ int   g_rankpart[B_ * JC_ * N_];
__device__ float g_partial[B_ * BLKS_PER_B_ * D_];

// predicated-accumulate count ops: ISETP (alu pipe) + @p FADD (fma pipe)
__device__ __forceinline__ void acc_ge_u(float& c, unsigned oj, unsigned oi) {
    asm("{.reg .pred p; setp.ge.u32 p, %1, %2; @p add.f32 %0, %0, 0f3F800000;}"
        : "+f"(c) : "r"(oj), "r"(oi));
}
__device__ __forceinline__ void acc_gt_u(float& c, unsigned oj, unsigned oi) {
    asm("{.reg .pred p; setp.gt.u32 p, %1, %2; @p add.f32 %0, %0, 0f3F800000;}"
        : "+f"(c) : "r"(oj), "r"(oi));
}
__device__ __forceinline__ unsigned ord32(float v) {
    unsigned bits = __float_as_uint(v);
    return (bits & 0x80000000u) ? ~bits : (bits | 0x80000000u);
}

// -------------------------------------------------------------------------
// Kernel A: partial descending rank (stable ties on index, matching
// jax.lax.top_k). grid (B, IC, JC) = 512 blocks, block 256; 4 i's/thread.
//   jc-chunk entirely below i-chunk : count ord_j >= ord_i   (j<i ties count)
//   jc-chunk entirely above         : count ord_j >  ord_i
//   overlapping chunk               : packed 44-bit key compare
//                                     (ord<<12)|(4095-idx) — single u64 '>'
//                                     == (vj>vi)||(vj==vi && j<i)
// -------------------------------------------------------------------------
__global__ void __launch_bounds__(256)
rank_part_kernel(const float* __restrict__ attn) {
    __shared__ alignas(16) unsigned sj[512];
    const int b  = blockIdx.x;
    const int ic = blockIdx.y;
    const int jc = blockIdx.z;
    const int t  = threadIdx.x;

    #pragma unroll
    for (int p = 0; p < 2; p++)
        sj[p * 256 + t] = ord32(attn[b * N_ + jc * 512 + p * 256 + t]);
    __syncthreads();

    unsigned oi[4];
    #pragma unroll
    for (int x = 0; x < 4; x++)
        oi[x] = ord32(attn[b * N_ + ic * 1024 + x * 256 + t]);

    int res[4];

    if ((jc >> 1) == ic) {
        // overlapping chunk: exact tie-break via packed keys
        unsigned long long ki[4];
        #pragma unroll
        for (int x = 0; x < 4; x++) {
            const int gi = ic * 1024 + x * 256 + t;
            ki[x] = ((unsigned long long)oi[x] << 12) | (unsigned)(4095 - gi);
        }
        int cnt[4] = {0, 0, 0, 0};
        #pragma unroll 4
        for (int j = 0; j < 512; j++) {
            const unsigned long long kj =
                ((unsigned long long)sj[j] << 12) |
                (unsigned)(4095 - (jc * 512 + j));
            #pragma unroll
            for (int x = 0; x < 4; x++) cnt[x] += (kj > ki[x]);
        }
        #pragma unroll
        for (int x = 0; x < 4; x++) res[x] = cnt[x];
    } else {
        float cf[4] = {0.f, 0.f, 0.f, 0.f};
        if (jc < ic * 2) {
            #pragma unroll 2
            for (int j4 = 0; j4 < 512; j4 += 4) {
                const uint4 v = *reinterpret_cast<const uint4*>(sj + j4);
                const unsigned vq[4] = {v.x, v.y, v.z, v.w};
                #pragma unroll
                for (int q = 0; q < 4; q++)
                    #pragma unroll
                    for (int x = 0; x < 4; x++)
                        acc_ge_u(cf[x], vq[q], oi[x]);
            }
        } else {
            #pragma unroll 2
            for (int j4 = 0; j4 < 512; j4 += 4) {
                const uint4 v = *reinterpret_cast<const uint4*>(sj + j4);
                const unsigned vq[4] = {v.x, v.y, v.z, v.w};
                #pragma unroll
                for (int q = 0; q < 4; q++)
                    #pragma unroll
                    for (int x = 0; x < 4; x++)
                        acc_gt_u(cf[x], vq[q], oi[x]);
            }
        }
        #pragma unroll
        for (int x = 0; x < 4; x++) res[x] = (int)cf[x];
    }

    #pragma unroll
    for (int x = 0; x < 4; x++)
        g_rankpart[(b * JC_ + jc) * N_ + ic * 1024 + x * 256 + t] = res[x];
}

// -------------------------------------------------------------------------
// Kernel B: fused gather + pruned-sum. grid (BLKS_PER_B, B), block 256.
// Streams TOK_ consecutive token rows (sequential 128KB read per block).
// Rank = inline sum of the 8 jc partials (uniform loads, amortized over
// a 4KB row). Per-token branch is uniform across the block:
//   rank < K : write row to out[b, rank, :]
//   else     : accumulate into per-thread float4 partial
// -------------------------------------------------------------------------
__global__ void __launch_bounds__(256)
fused_kernel(const float* __restrict__ seq, float* __restrict__ out) {
    const int b   = blockIdx.y;
    const int blk = blockIdx.x;
    const int t   = threadIdx.x;
    const int n0  = blk * TOK_;

    const float4* __restrict__ src =
        reinterpret_cast<const float4*>(seq + ((size_t)(b * N_ + n0)) * D_);
    const int* __restrict__ rp = g_rankpart + b * JC_ * N_ + n0;

    float4 acc = make_float4(0.f, 0.f, 0.f, 0.f);

    #pragma unroll 8
    for (int k = 0; k < TOK_; k++) {
        const float4 v = src[k * (D_ / 4) + t];
        int r = 0;
        #pragma unroll
        for (int jc = 0; jc < JC_; jc++) r += rp[jc * N_ + k];
        if (r < K_) {
            reinterpret_cast<float4*>(
                out + ((size_t)(b * (K_ + 1) + r)) * D_)[t] = v;
        } else {
            acc.x += v.x; acc.y += v.y; acc.z += v.z; acc.w += v.w;
        }
    }

    reinterpret_cast<float4*>(g_partial)
        [((size_t)b * BLKS_PER_B_ + blk) * (D_ / 4) + t] = acc;
}

// -------------------------------------------------------------------------
// Kernel C: reduce partials, write mixup row out[b, K, :].
// grid (B, 16), block 256. rem_cnt = 2048 + 1e-10 == 2048.0f in fp32.
// -------------------------------------------------------------------------
__global__ void __launch_bounds__(256)
rem_kernel(float* __restrict__ out) {
    const int b  = blockIdx.x;
    const int g  = threadIdx.x & 15;
    const int s  = threadIdx.x >> 4;
    const int c4 = blockIdx.y * 16 + g;

    const float4* __restrict__ p =
        reinterpret_cast<const float4*>(g_partial) +
        (size_t)b * BLKS_PER_B_ * (D_ / 4) + c4;

    float4 a = make_float4(0.f, 0.f, 0.f, 0.f);
    #pragma unroll
    for (int m = 0; m < 8; m++) {
        const float4 v = p[(size_t)(s + 16 * m) * (D_ / 4)];
        a.x += v.x; a.y += v.y; a.z += v.z; a.w += v.w;
    }

    __shared__ float4 red[16][16];
    red[s][g] = a;
    __syncthreads();

    #pragma unroll
    for (int step = 8; step >= 1; step >>= 1) {
        if (s < step) {
            float4 o = red[s + step][g];
            red[s][g].x += o.x; red[s][g].y += o.y;
            red[s][g].z += o.z; red[s][g].w += o.w;
        }
        __syncthreads();
    }

    if (s == 0) {
        const float sc = 0.05f / 2048.0f;
        float4 r = red[0][g];
        r.x *= sc; r.y *= sc; r.z *= sc; r.w *= sc;
        reinterpret_cast<float4*>(
            out + ((size_t)(b * (K_ + 1) + K_)) * D_)[c4] = r;
    }
}

extern "C" void kernel_launch(void* const* d_in, const int* in_sizes, int n_in,
                              void* d_out, int out_size) {
    const float* seq  = (const float*)d_in[0];   // (16, 4096, 1024) fp32
    const float* attn = (const float*)d_in[1];   // (16, 4096) fp32
    float* out = (float*)d_out;                  // (16, 2049, 1024) fp32
    (void)in_sizes; (void)n_in; (void)out_size;

    rank_part_kernel<<<dim3(B_, IC_, JC_), 256>>>(attn);
    fused_kernel    <<<dim3(BLKS_PER_B_, B_), 256>>>(seq, out);
    rem_kernel      <<<dim3(B_, 16), 256>>>(out);
}

// round 5
// speedup vs baseline: 1.9713x; 1.1585x over previous
#include <cuda_runtime.h>

#define B_  16
#define N_  4096
#define D_  1024
#define K_  2048

#define TOK_ 32          // tokens per fused block
#define BLKS_PER_B_ (N_ / TOK_)   // 128

__device__ int   g_rank[B_ * N_];
__device__ float g_partial[B_ * BLKS_PER_B_ * D_];

__device__ __forceinline__ unsigned ord32(float v) {
    unsigned bits = __float_as_uint(v);
    return (bits & 0x80000000u) ? ~bits : (bits | 0x80000000u);
}

// -------------------------------------------------------------------------
// Kernel A: per-batch bitonic sort -> exact descending rank.
// grid (B), block 1024, 32KB smem of u64 keys.
// key = (ord32(v) << 12) | (4095 - idx): descending u64 order reproduces
// jax.lax.top_k exactly (descending by value, ties by smaller index first),
// and all keys are unique. Sorted position == rank; scatter rank[idx] = pos.
// -------------------------------------------------------------------------
__global__ void __launch_bounds__(1024)
sort_rank_kernel(const float* __restrict__ attn) {
    __shared__ unsigned long long sk[N_];
    const int b = blockIdx.x;
    const int t = threadIdx.x;

    #pragma unroll
    for (int p = 0; p < N_ / 1024; p++) {
        const int i = p * 1024 + t;
        sk[i] = ((unsigned long long)ord32(attn[b * N_ + i]) << 12) |
                (unsigned)(4095 - i);
    }
    __syncthreads();

    for (int k = 2; k <= N_; k <<= 1) {
        for (int j = k >> 1; j > 0; j >>= 1) {
            #pragma unroll
            for (int q = 0; q < 2; q++) {
                const int tid = q * 1024 + t;           // pair id 0..2047
                const int i   = 2 * tid - (tid & (j - 1));
                const int ixj = i + j;
                const bool desc = ((i & k) == 0);
                const unsigned long long a = sk[i];
                const unsigned long long c = sk[ixj];
                const bool swap = desc ? (a < c) : (a > c);
                if (swap) { sk[i] = c; sk[ixj] = a; }
            }
            __syncthreads();
        }
    }

    #pragma unroll
    for (int p = 0; p < N_ / 1024; p++) {
        const int pos = p * 1024 + t;
        const int idx = 4095 - (int)(sk[pos] & 0xFFFu);
        g_rank[b * N_ + idx] = pos;
    }
}

// -------------------------------------------------------------------------
// Kernel B: fused gather + pruned-sum. grid (BLKS_PER_B, B), block 256.
// Streams TOK_ consecutive token rows (sequential 128KB read per block).
// Per-token branch is uniform across the block (no divergence):
//   rank < K : write row to out[b, rank, :]
//   else     : accumulate into per-thread float4 partial
// -------------------------------------------------------------------------
__global__ void __launch_bounds__(256)
fused_kernel(const float* __restrict__ seq, float* __restrict__ out) {
    const int b   = blockIdx.y;
    const int blk = blockIdx.x;
    const int t   = threadIdx.x;
    const int n0  = blk * TOK_;

    const float4* __restrict__ src =
        reinterpret_cast<const float4*>(seq + ((size_t)(b * N_ + n0)) * D_);
    const int* __restrict__ rnk = g_rank + b * N_ + n0;

    float4 acc = make_float4(0.f, 0.f, 0.f, 0.f);

    #pragma unroll 8
    for (int k = 0; k < TOK_; k++) {
        const float4 v = src[k * (D_ / 4) + t];
        const int r = rnk[k];
        if (r < K_) {
            reinterpret_cast<float4*>(
                out + ((size_t)(b * (K_ + 1) + r)) * D_)[t] = v;
        } else {
            acc.x += v.x; acc.y += v.y; acc.z += v.z; acc.w += v.w;
        }
    }

    reinterpret_cast<float4*>(g_partial)
        [((size_t)b * BLKS_PER_B_ + blk) * (D_ / 4) + t] = acc;
}

// -------------------------------------------------------------------------
// Kernel C: reduce partials, write mixup row out[b, K, :].
// grid (B, 16), block 256. rem_cnt = 2048 + 1e-10 == 2048.0f in fp32.
// -------------------------------------------------------------------------
__global__ void __launch_bounds__(256)
rem_kernel(float* __restrict__ out) {
    const int b  = blockIdx.x;
    const int g  = threadIdx.x & 15;
    const int s  = threadIdx.x >> 4;
    const int c4 = blockIdx.y * 16 + g;

    const float4* __restrict__ p =
        reinterpret_cast<const float4*>(g_partial) +
        (size_t)b * BLKS_PER_B_ * (D_ / 4) + c4;

    float4 a = make_float4(0.f, 0.f, 0.f, 0.f);
    #pragma unroll
    for (int m = 0; m < 8; m++) {
        const float4 v = p[(size_t)(s + 16 * m) * (D_ / 4)];
        a.x += v.x; a.y += v.y; a.z += v.z; a.w += v.w;
    }

    __shared__ float4 red[16][16];
    red[s][g] = a;
    __syncthreads();

    #pragma unroll
    for (int step = 8; step >= 1; step >>= 1) {
        if (s < step) {
            float4 o = red[s + step][g];
            red[s][g].x += o.x; red[s][g].y += o.y;
            red[s][g].z += o.z; red[s][g].w += o.w;
        }
        __syncthreads();
    }

    if (s == 0) {
        const float sc = 0.05f / 2048.0f;
        float4 r = red[0][g];
        r.x *= sc; r.y *= sc; r.z *= sc; r.w *= sc;
        reinterpret_cast<float4*>(
            out + ((size_t)(b * (K_ + 1) + K_)) * D_)[c4] = r;
    }
}

extern "C" void kernel_launch(void* const* d_in, const int* in_sizes, int n_in,
                              void* d_out, int out_size) {
    const float* seq  = (const float*)d_in[0];   // (16, 4096, 1024) fp32
    const float* attn = (const float*)d_in[1];   // (16, 4096) fp32
    float* out = (float*)d_out;                  // (16, 2049, 1024) fp32
    (void)in_sizes; (void)n_in; (void)out_size;

    sort_rank_kernel<<<B_, 1024>>>(attn);
    fused_kernel    <<<dim3(BLKS_PER_B_, B_), 256>>>(seq, out);
    rem_kernel      <<<dim3(B_, 16), 256>>>(out);
}